// round 12
// baseline (speedup 1.0000x reference)
#include <cuda_runtime.h>
#include <math.h>
#include <stdint.h>

#define BB 2
#define LL 384
#define DD 256
#define HH 8
#define DHH 32

// Scratch (device globals — no allocation allowed). 16B-aligned: float4 access.
__device__ __align__(16) float g_KP[BB*HH*LL*DHH];   // [b][h][l][dh]
__device__ __align__(16) float g_VP[BB*HH*LL*DHH];   // [b][h][l][dh]
__device__ __align__(16) float g_QU[BB*LL*DD];       // [b][l][h*32+dh]  (q + u)
__device__ __align__(16) float g_QV[BB*LL*DD];       // [b][l][h*32+dh]  (q + v)
__device__ __align__(16) float g_W [BB*LL*HH*DD];    // [b][q][h][d]
__device__ __align__(16) float g_AC[BB*HH*LL*LL];    // [b][h][q][k]  content term A+C
__device__ __align__(16) float g_SC[BB*HH*LL*LL];    // [b][h][q][k]  raw scores

// ---------------------------------------------------------------------------
// Kernel 1: fused Q/K/V projections.  out = X @ W.T + b  (M=768, N=256, K=256)
// ---------------------------------------------------------------------------
__global__ void __launch_bounds__(256) proj_kernel(
    const float* __restrict__ key,   const float* __restrict__ query,
    const float* __restrict__ value,
    const float* __restrict__ Wk, const float* __restrict__ bk,
    const float* __restrict__ Wq, const float* __restrict__ bq,
    const float* __restrict__ Wv, const float* __restrict__ bv,
    const float* __restrict__ u,  const float* __restrict__ vvec)
{
    const int z = blockIdx.z;
    const float* X    = (z == 0) ? key : (z == 1) ? query : value;
    const float* Wt   = (z == 0) ? Wk  : (z == 1) ? Wq    : Wv;
    const float* bias = (z == 0) ? bk  : (z == 1) ? bq    : bv;

    const int m0 = blockIdx.x * 32;
    const int n0 = blockIdx.y * 64;
    const int tid = threadIdx.x;
    const int tx = tid % 16, ty = tid / 16;

    __shared__ float a_sm[32 * 65];
    __shared__ float b_sm[64 * 68];

    float acc[2][4] = {};

    const int lr = tid / 16;
    const int lc = (tid % 16) * 4;

    for (int kt = 0; kt < DD; kt += 64) {
        {
            float4 va = *(const float4*)(X + (m0 + lr) * DD + kt + lc);
            float* d0 = a_sm + lr * 65 + lc;
            d0[0] = va.x; d0[1] = va.y; d0[2] = va.z; d0[3] = va.w;
            float4 vb = *(const float4*)(X + (m0 + lr + 16) * DD + kt + lc);
            float* d1 = a_sm + (lr + 16) * 65 + lc;
            d1[0] = vb.x; d1[1] = vb.y; d1[2] = vb.z; d1[3] = vb.w;
        }
        #pragma unroll
        for (int j = 0; j < 4; j++) {
            int nr = lr + 16 * j;
            float4 vb = *(const float4*)(Wt + (n0 + nr) * DD + kt + lc);
            b_sm[(lc + 0) * 68 + nr] = vb.x;
            b_sm[(lc + 1) * 68 + nr] = vb.y;
            b_sm[(lc + 2) * 68 + nr] = vb.z;
            b_sm[(lc + 3) * 68 + nr] = vb.w;
        }
        __syncthreads();
        #pragma unroll
        for (int k = 0; k < 64; k++) {
            float a0 = a_sm[ty * 65 + k];
            float a1 = a_sm[(ty + 16) * 65 + k];
            float4 bf = *(const float4*)(b_sm + k * 68 + tx * 4);
            acc[0][0] += a0 * bf.x; acc[0][1] += a0 * bf.y; acc[0][2] += a0 * bf.z; acc[0][3] += a0 * bf.w;
            acc[1][0] += a1 * bf.x; acc[1][1] += a1 * bf.y; acc[1][2] += a1 * bf.z; acc[1][3] += a1 * bf.w;
        }
        __syncthreads();
    }

    #pragma unroll
    for (int i = 0; i < 2; i++) {
        int m = m0 + ty + 16 * i;
        int b = m / LL, l = m % LL;
        #pragma unroll
        for (int j = 0; j < 4; j++) {
            int jc = n0 + tx * 4 + j;
            float val = acc[i][j] + bias[jc];
            int h = jc / DHH, dh = jc % DHH;
            if (z == 0) {
                g_KP[((b * HH + h) * LL + l) * DHH + dh] = val;
            } else if (z == 2) {
                g_VP[((b * HH + h) * LL + l) * DHH + dh] = val;
            } else {
                g_QU[m * DD + jc] = val + u[jc];
                g_QV[m * DD + jc] = val + vvec[jc];
            }
        }
    }
}

// ---------------------------------------------------------------------------
// Kernel 2: W[b,q,h,:] = sum_dh QV[b,q,h,dh] * Wr[h*32+dh, :]
// ---------------------------------------------------------------------------
__global__ void __launch_bounds__(256) w_kernel(const float* __restrict__ Wr)
{
    const int h  = blockIdx.z;
    const int m0 = blockIdx.x * 64;
    const int n0 = blockIdx.y * 64;
    const int tid = threadIdx.x;
    const int tx = tid % 16, ty = tid / 16;

    __shared__ float a_sm[64 * 33];
    __shared__ float b_sm[32 * 68];

    {
        int r = tid / 4, cb = (tid % 4) * 8;
        #pragma unroll
        for (int cc = 0; cc < 8; cc += 4) {
            float4 va = *(const float4*)(g_QV + (m0 + r) * DD + h * DHH + cb + cc);
            float* dst = a_sm + r * 33 + cb + cc;
            dst[0] = va.x; dst[1] = va.y; dst[2] = va.z; dst[3] = va.w;
        }
    }
    {
        int k = tid / 8, cb = (tid % 8) * 8;
        #pragma unroll
        for (int cc = 0; cc < 8; cc += 4) {
            float4 vb = *(const float4*)(Wr + (h * DHH + k) * DD + n0 + cb + cc);
            *(float4*)(b_sm + k * 68 + cb + cc) = vb;
        }
    }
    __syncthreads();

    float acc[4][4] = {};
    #pragma unroll
    for (int k = 0; k < 32; k++) {
        float a0 = a_sm[(ty * 4 + 0) * 33 + k];
        float a1 = a_sm[(ty * 4 + 1) * 33 + k];
        float a2 = a_sm[(ty * 4 + 2) * 33 + k];
        float a3 = a_sm[(ty * 4 + 3) * 33 + k];
        float4 bf = *(const float4*)(b_sm + k * 68 + tx * 4);
        acc[0][0] += a0 * bf.x; acc[0][1] += a0 * bf.y; acc[0][2] += a0 * bf.z; acc[0][3] += a0 * bf.w;
        acc[1][0] += a1 * bf.x; acc[1][1] += a1 * bf.y; acc[1][2] += a1 * bf.z; acc[1][3] += a1 * bf.w;
        acc[2][0] += a2 * bf.x; acc[2][1] += a2 * bf.y; acc[2][2] += a2 * bf.z; acc[2][3] += a2 * bf.w;
        acc[3][0] += a3 * bf.x; acc[3][1] += a3 * bf.y; acc[3][2] += a3 * bf.z; acc[3][3] += a3 * bf.w;
    }

    #pragma unroll
    for (int i = 0; i < 4; i++) {
        int bq = m0 + ty * 4 + i;
        #pragma unroll
        for (int j = 0; j < 4; j++) {
            g_W[((size_t)bq * HH + h) * DD + n0 + tx * 4 + j] = acc[i][j];
        }
    }
}

// ---------------------------------------------------------------------------
// Kernel 2b: content term  AC[b,h,q,k] = sum_dh QU[b,q,h,dh] * KP[b,h,k,dh]
// ---------------------------------------------------------------------------
__global__ void __launch_bounds__(256) ac_kernel()
{
    const int bh = blockIdx.z;
    const int b = bh / HH, h = bh % HH;
    const int q0 = blockIdx.x * 64;
    const int k0 = blockIdx.y * 64;
    const int tid = threadIdx.x;
    const int tx = tid % 16, ty = tid / 16;

    __shared__ float a_sm[64 * 33];   // [q][d]
    __shared__ float b_sm[32 * 68];   // [d][k]

    {
        int r = tid / 4, cb = (tid % 4) * 8;
        #pragma unroll
        for (int cc = 0; cc < 8; cc += 4) {
            float4 va = *(const float4*)(g_QU + ((b * LL + q0 + r)) * DD + h * DHH + cb + cc);
            float* dst = a_sm + r * 33 + cb + cc;
            dst[0] = va.x; dst[1] = va.y; dst[2] = va.z; dst[3] = va.w;
        }
    }
    {
        int r = tid / 4, cb = (tid % 4) * 8;
        #pragma unroll
        for (int cc = 0; cc < 8; cc += 4) {
            float4 vb = *(const float4*)(g_KP + ((size_t)(b * HH + h) * LL + k0 + r) * DHH + cb + cc);
            b_sm[(cb + cc + 0) * 68 + r] = vb.x;
            b_sm[(cb + cc + 1) * 68 + r] = vb.y;
            b_sm[(cb + cc + 2) * 68 + r] = vb.z;
            b_sm[(cb + cc + 3) * 68 + r] = vb.w;
        }
    }
    __syncthreads();

    float acc[4][4] = {};
    #pragma unroll
    for (int k = 0; k < 32; k++) {
        float a0 = a_sm[(ty * 4 + 0) * 33 + k];
        float a1 = a_sm[(ty * 4 + 1) * 33 + k];
        float a2 = a_sm[(ty * 4 + 2) * 33 + k];
        float a3 = a_sm[(ty * 4 + 3) * 33 + k];
        float4 bf = *(const float4*)(b_sm + k * 68 + tx * 4);
        acc[0][0] += a0 * bf.x; acc[0][1] += a0 * bf.y; acc[0][2] += a0 * bf.z; acc[0][3] += a0 * bf.w;
        acc[1][0] += a1 * bf.x; acc[1][1] += a1 * bf.y; acc[1][2] += a1 * bf.z; acc[1][3] += a1 * bf.w;
        acc[2][0] += a2 * bf.x; acc[2][1] += a2 * bf.y; acc[2][2] += a2 * bf.z; acc[2][3] += a2 * bf.w;
        acc[3][0] += a3 * bf.x; acc[3][1] += a3 * bf.y; acc[3][2] += a3 * bf.z; acc[3][3] += a3 * bf.w;
    }

    #pragma unroll
    for (int i = 0; i < 4; i++) {
        int qg = q0 + ty * 4 + i;
        #pragma unroll
        for (int j = 0; j < 4; j++) {
            g_AC[((size_t)bh * LL + qg) * LL + k0 + tx * 4 + j] = acc[i][j];
        }
    }
}

// ---------------------------------------------------------------------------
// Kernel 3: score_kernel. Block per (q,b). Each pos element read ONCE.
// KT2=16-row tiles, cp.async double-buffered. warp = d-group; lane = (k, half).
// Scores (incl. AC + ccp + mask) written to g_SC. 45.8 KB smem -> 4 blocks/SM.
// ---------------------------------------------------------------------------
#define KT2 16
#define NT2 (LL/KT2)    // 24
#define P4  65          // float4 stride per staged pos row (conflict-free)

__global__ void __launch_bounds__(256, 4) score_kernel(
    const float* __restrict__ pos,
    const float* __restrict__ key_mask,
    const float* __restrict__ br)
{
    __shared__ __align__(16) float posbuf[2 * KT2 * P4 * 4];  // 33.3 KB
    __shared__ __align__(16) float red[KT2 * 68];             // 4.3 KB
    __shared__ __align__(16) float w_sm[HH * DD];             // 8 KB

    const int q = blockIdx.x, b = blockIdx.y;
    const int tid = threadIdx.x;
    const int wid = tid >> 5, lane = tid & 31;
    const int kr = lane & 15, half = lane >> 4;

    const float* posb = pos + ((size_t)(b * LL + q)) * LL * DD;

    // prefetch tile 0 (16 rows x 64 float4 = 1024; 4 per thread)
    {
        const float4* src = (const float4*)posb;
        uint32_t dst0 = (uint32_t)__cvta_generic_to_shared(posbuf);
        #pragma unroll
        for (int i = 0; i < 4; i++) {
            int idx = tid + i * 256;
            int row = idx >> 6, c = idx & 63;
            asm volatile("cp.async.cg.shared.global [%0], [%1], 16;\n"
                         :: "r"(dst0 + (uint32_t)(row * P4 + c) * 16), "l"(src + idx));
        }
        asm volatile("cp.async.commit_group;\n");
    }

    // W slice for this (b,q)
    {
        const float4* wsrc = (const float4*)(g_W + ((size_t)(b * LL + q)) * HH * DD);
        float4* wdst = (float4*)w_sm;
        wdst[tid]       = wsrc[tid];
        wdst[tid + 256] = wsrc[tid + 256];
    }

    // ccp for head wid = (q+v).br, kept in registers (warp wid == head wid)
    float ccp;
    {
        float c = g_QV[(b * LL + q) * DD + wid * DHH + lane] * br[wid * DHH + lane];
        #pragma unroll
        for (int off = 16; off; off >>= 1)
            c += __shfl_xor_sync(0xffffffffu, c, off);
        ccp = c;
    }

    const float scale = 0.17677669529663687f;  // 1/sqrt(32)
    const float* acrow = g_AC + ((size_t)(b * HH + wid) * LL + q) * LL;
    float*       scrow = g_SC + ((size_t)(b * HH + wid) * LL + q) * LL;

    for (int t = 0; t < NT2; t++) {
        if (t + 1 < NT2) {
            const float4* src = (const float4*)(posb + (size_t)(t + 1) * KT2 * DD);
            uint32_t dstb = (uint32_t)__cvta_generic_to_shared(posbuf + ((t + 1) & 1) * KT2 * P4 * 4);
            #pragma unroll
            for (int i = 0; i < 4; i++) {
                int idx = tid + i * 256;
                int row = idx >> 6, c = idx & 63;
                asm volatile("cp.async.cg.shared.global [%0], [%1], 16;\n"
                             :: "r"(dstb + (uint32_t)(row * P4 + c) * 16), "l"(src + idx));
            }
            asm volatile("cp.async.commit_group;\n");
            asm volatile("cp.async.wait_group 1;\n");
        } else {
            asm volatile("cp.async.wait_group 0;\n");
        }
        __syncthreads();

        // partial dot: thread (dg=wid, k=kr, half): 4 float4 chunks of its d-slice
        const float* prow = posbuf + (t & 1) * KT2 * P4 * 4 + kr * P4 * 4 + (wid * 8 + half * 4) * 4;
        float acc[8] = {0.f, 0.f, 0.f, 0.f, 0.f, 0.f, 0.f, 0.f};
        #pragma unroll
        for (int d4 = 0; d4 < 4; d4++) {
            float4 p = *(const float4*)(prow + d4 * 4);
            const float* wb = w_sm + (wid * 8 + half * 4 + d4) * 4;
            #pragma unroll
            for (int h = 0; h < 8; h++) {
                float4 w = *(const float4*)(wb + h * DD);   // warp-uniform broadcast
                acc[h] = fmaf(p.x, w.x, fmaf(p.y, w.y, fmaf(p.z, w.z, fmaf(p.w, w.w, acc[h]))));
            }
        }
        // combine halves (lane ^ 16 has same k, other half of d-slice)
        #pragma unroll
        for (int h = 0; h < 8; h++)
            acc[h] += __shfl_xor_sync(0xffffffffu, acc[h], 16);
        if (half == 0) {
            *(float4*)(red + kr * 68 + wid * 8)     = make_float4(acc[0], acc[1], acc[2], acc[3]);
            *(float4*)(red + kr * 68 + wid * 8 + 4) = make_float4(acc[4], acc[5], acc[6], acc[7]);
        }
        __syncthreads();

        // reduce across 8 d-groups; warp wid acts as head, lanes 0..15 -> k
        if (lane < 16) {
            float s = 0.f;
            #pragma unroll
            for (int dg = 0; dg < 8; dg++)
                s += red[lane * 68 + dg * 8 + wid];
            int kg = t * KT2 + lane;
            float pm = (1.0f - key_mask[b * LL + kg]) * 1e15f;
            scrow[kg] = (s + acrow[kg] + ccp) * scale - pm;
        }
        // no trailing barrier: red is next written only after the next
        // iteration's __syncthreads()
    }
}

// ---------------------------------------------------------------------------
// Kernel 4: softmax + attn@V. Block per (q,b), warp = head. Warp-private.
// ---------------------------------------------------------------------------
__global__ void __launch_bounds__(256) sm_kernel(float* __restrict__ out)
{
    __shared__ float sc[HH][LL];
    const int q = blockIdx.x, b = blockIdx.y;
    const int wid = threadIdx.x >> 5, lane = threadIdx.x & 31;

    const float* srow = g_SC + ((size_t)(b * HH + wid) * LL + q) * LL;

    float v[LL / 32];
    float m = -1e30f;
    #pragma unroll
    for (int i = 0; i < LL / 32; i++) {
        v[i] = srow[lane + i * 32];
        m = fmaxf(m, v[i]);
    }
    #pragma unroll
    for (int off = 16; off; off >>= 1)
        m = fmaxf(m, __shfl_xor_sync(0xffffffffu, m, off));

    float s = 0.f;
    #pragma unroll
    for (int i = 0; i < LL / 32; i++) {
        float e = __expf(v[i] - m);
        sc[wid][lane + i * 32] = e;
        s += e;
    }
    #pragma unroll
    for (int off = 16; off; off >>= 1)
        s += __shfl_xor_sync(0xffffffffu, s, off);
    const float rinv = 1.0f / s;
    __syncwarp();

    float acc = 0.f;
    const float* vp = g_VP + ((size_t)(b * HH + wid)) * LL * DHH + lane;
    #pragma unroll 4
    for (int k = 0; k < LL; k++)
        acc += sc[wid][k] * vp[k * DHH];

    out[(b * LL + q) * DD + wid * DHH + lane] = acc * rinv;
}

// ---------------------------------------------------------------------------
extern "C" void kernel_launch(void* const* d_in, const int* in_sizes, int n_in,
                              void* d_out, int out_size)
{
    const float* key      = (const float*)d_in[0];
    const float* query    = (const float*)d_in[1];
    const float* value    = (const float*)d_in[2];
    const float* pos      = (const float*)d_in[3];
    const float* key_mask = (const float*)d_in[4];
    const float* Wk = (const float*)d_in[5];
    const float* bk = (const float*)d_in[6];
    const float* Wq = (const float*)d_in[7];
    const float* bq = (const float*)d_in[8];
    const float* Wv = (const float*)d_in[9];
    const float* bv = (const float*)d_in[10];
    const float* Wr = (const float*)d_in[11];
    const float* br = (const float*)d_in[12];
    const float* u  = (const float*)d_in[13];
    const float* v  = (const float*)d_in[14];
    float* out = (float*)d_out;

    proj_kernel<<<dim3(24, 4, 3), 256>>>(key, query, value, Wk, bk, Wq, bq, Wv, bv, u, v);
    w_kernel<<<dim3(12, 4, 8), 256>>>(Wr);
    ac_kernel<<<dim3(6, 6, 16), 256>>>();
    score_kernel<<<dim3(LL, BB), 256>>>(pos, key_mask, br);
    sm_kernel<<<dim3(LL, BB), 256>>>(out);
}

// round 13
// speedup vs baseline: 1.5884x; 1.5884x over previous
#include <cuda_runtime.h>
#include <math.h>
#include <stdint.h>

#define BB 2
#define LL 384
#define DD 256
#define HH 8
#define DHH 32
#define FULLM 0xffffffffu

#define SCALE 0.17677669529663687f   // 1/sqrt(32)
#define INV_SCALE 5.656854249492381f

// Scratch (device globals — no allocation allowed). 16B-aligned: float4 access.
__device__ __align__(16) float g_KP[BB*HH*LL*DHH];   // [b][h][l][dh]
__device__ __align__(16) float g_VP[BB*HH*LL*DHH];   // [b][h][l][dh]
__device__ __align__(16) float g_QU[BB*LL*DD];       // [b][l][h*32+dh]  (q + u)
__device__ __align__(16) float g_QV[BB*LL*DD];       // [b][l][h*32+dh]  (q + v)
__device__ __align__(16) float g_W [BB*LL*HH*DD];    // [b][q][h][d]
__device__ __align__(16) float g_CCP[BB*LL*HH];      // [bq][h]  (q+v).br
__device__ __align__(16) float g_AC[BB*HH*LL*LL];    // [b][h][q][k]  AC + ccp - pm/scale
__device__ __align__(16) float g_SC[BB*HH*LL*LL];    // [b][h][q][k]  scores -> probs

// f32x2 packed helpers
__device__ __forceinline__ unsigned long long pk2(float lo, float hi) {
    unsigned long long r;
    asm("mov.b64 %0, {%1, %2};" : "=l"(r) : "f"(lo), "f"(hi));
    return r;
}
__device__ __forceinline__ unsigned long long mul2(unsigned long long a, unsigned long long b) {
    unsigned long long r;
    asm("mul.rn.f32x2 %0, %1, %2;" : "=l"(r) : "l"(a), "l"(b));
    return r;
}
__device__ __forceinline__ unsigned long long fma2(unsigned long long a, unsigned long long b, unsigned long long c) {
    unsigned long long r;
    asm("fma.rn.f32x2 %0, %1, %2, %3;" : "=l"(r) : "l"(a), "l"(b), "l"(c));
    return r;
}
__device__ __forceinline__ float upk_sum(unsigned long long v) {
    float lo, hi;
    asm("mov.b64 {%0, %1}, %2;" : "=f"(lo), "=f"(hi) : "l"(v));
    return lo + hi;
}

// ---------------------------------------------------------------------------
// Kernel 1: fused Q/K/V projections.  out = X @ W.T + b  (M=768, N=256, K=256)
// 32x32 tile, K-chunk 64. grid (24, 8, 3) = 576 blocks (was grid-limited).
// ---------------------------------------------------------------------------
__global__ void __launch_bounds__(256) proj_kernel(
    const float* __restrict__ key,   const float* __restrict__ query,
    const float* __restrict__ value,
    const float* __restrict__ Wk, const float* __restrict__ bk,
    const float* __restrict__ Wq, const float* __restrict__ bq,
    const float* __restrict__ Wv, const float* __restrict__ bv,
    const float* __restrict__ u,  const float* __restrict__ vvec)
{
    const int z = blockIdx.z;
    const float* X    = (z == 0) ? key : (z == 1) ? query : value;
    const float* Wt   = (z == 0) ? Wk  : (z == 1) ? Wq    : Wv;
    const float* bias = (z == 0) ? bk  : (z == 1) ? bq    : bv;

    const int m0 = blockIdx.x * 32;
    const int n0 = blockIdx.y * 32;
    const int tid = threadIdx.x;
    const int tx = tid % 8, ty = tid / 8;   // tx: n/4 (0..7), ty: q row (0..31)

    __shared__ float a_sm[32 * 65];   // [row][k]
    __shared__ float b_sm[64 * 36];   // [k][n]

    float acc[4] = {};

    const int lr = tid / 16;          // 0..15
    const int lc = (tid % 16) * 4;    // 0..60

    for (int kt = 0; kt < DD; kt += 64) {
        // A tile: 32 rows x 64 k
        {
            float4 va = *(const float4*)(X + (m0 + lr) * DD + kt + lc);
            float* d0 = a_sm + lr * 65 + lc;
            d0[0] = va.x; d0[1] = va.y; d0[2] = va.z; d0[3] = va.w;
            float4 vb = *(const float4*)(X + (m0 + lr + 16) * DD + kt + lc);
            float* d1 = a_sm + (lr + 16) * 65 + lc;
            d1[0] = vb.x; d1[1] = vb.y; d1[2] = vb.z; d1[3] = vb.w;
        }
        // B tile: 32 n-rows x 64 k, transposed into [k][n]
        #pragma unroll
        for (int j = 0; j < 2; j++) {
            int nr = lr + 16 * j;
            float4 vb = *(const float4*)(Wt + (n0 + nr) * DD + kt + lc);
            b_sm[(lc + 0) * 36 + nr] = vb.x;
            b_sm[(lc + 1) * 36 + nr] = vb.y;
            b_sm[(lc + 2) * 36 + nr] = vb.z;
            b_sm[(lc + 3) * 36 + nr] = vb.w;
        }
        __syncthreads();
        #pragma unroll
        for (int k = 0; k < 64; k++) {
            float a0 = a_sm[ty * 65 + k];
            float4 bf = *(const float4*)(b_sm + k * 36 + tx * 4);
            acc[0] += a0 * bf.x; acc[1] += a0 * bf.y; acc[2] += a0 * bf.z; acc[3] += a0 * bf.w;
        }
        __syncthreads();
    }

    const int m = m0 + ty;
    const int b = m / LL, l = m % LL;
    #pragma unroll
    for (int j = 0; j < 4; j++) {
        int jc = n0 + tx * 4 + j;
        float val = acc[j] + bias[jc];
        int h = jc / DHH, dh = jc % DHH;
        if (z == 0) {
            g_KP[((b * HH + h) * LL + l) * DHH + dh] = val;
        } else if (z == 2) {
            g_VP[((b * HH + h) * LL + l) * DHH + dh] = val;
        } else {
            g_QU[m * DD + jc] = val + u[jc];
            g_QV[m * DD + jc] = val + vvec[jc];
        }
    }
}

// ---------------------------------------------------------------------------
// Kernel 2: W[b,q,h,:] = sum_dh QV[b,q,h,dh] * Wr[h*32+dh, :]
// Also computes g_CCP[bq][h] = QV(head slice) . br(head slice) when by==0.
// ---------------------------------------------------------------------------
__global__ void __launch_bounds__(256) w_kernel(const float* __restrict__ Wr,
                                               const float* __restrict__ br)
{
    const int h  = blockIdx.z;
    const int m0 = blockIdx.x * 64;
    const int n0 = blockIdx.y * 64;
    const int tid = threadIdx.x;
    const int tx = tid % 16, ty = tid / 16;

    __shared__ float a_sm[64 * 33];
    __shared__ float b_sm[32 * 68];

    {
        int r = tid / 4, cb = (tid % 4) * 8;
        #pragma unroll
        for (int cc = 0; cc < 8; cc += 4) {
            float4 va = *(const float4*)(g_QV + (m0 + r) * DD + h * DHH + cb + cc);
            float* dst = a_sm + r * 33 + cb + cc;
            dst[0] = va.x; dst[1] = va.y; dst[2] = va.z; dst[3] = va.w;
        }
    }
    {
        int k = tid / 8, cb = (tid % 8) * 8;
        #pragma unroll
        for (int cc = 0; cc < 8; cc += 4) {
            float4 vb = *(const float4*)(Wr + (h * DHH + k) * DD + n0 + cb + cc);
            *(float4*)(b_sm + k * 68 + cb + cc) = vb;
        }
    }
    __syncthreads();

    // ccp (once per (m0,h))
    if (blockIdx.y == 0 && tid < 64) {
        float s = 0.f;
        #pragma unroll
        for (int d = 0; d < DHH; d++)
            s += a_sm[tid * 33 + d] * br[h * DHH + d];
        g_CCP[(m0 + tid) * HH + h] = s;
    }

    float acc[4][4] = {};
    #pragma unroll
    for (int k = 0; k < 32; k++) {
        float a0 = a_sm[(ty * 4 + 0) * 33 + k];
        float a1 = a_sm[(ty * 4 + 1) * 33 + k];
        float a2 = a_sm[(ty * 4 + 2) * 33 + k];
        float a3 = a_sm[(ty * 4 + 3) * 33 + k];
        float4 bf = *(const float4*)(b_sm + k * 68 + tx * 4);
        acc[0][0] += a0 * bf.x; acc[0][1] += a0 * bf.y; acc[0][2] += a0 * bf.z; acc[0][3] += a0 * bf.w;
        acc[1][0] += a1 * bf.x; acc[1][1] += a1 * bf.y; acc[1][2] += a1 * bf.z; acc[1][3] += a1 * bf.w;
        acc[2][0] += a2 * bf.x; acc[2][1] += a2 * bf.y; acc[2][2] += a2 * bf.z; acc[2][3] += a2 * bf.w;
        acc[3][0] += a3 * bf.x; acc[3][1] += a3 * bf.y; acc[3][2] += a3 * bf.z; acc[3][3] += a3 * bf.w;
    }

    #pragma unroll
    for (int i = 0; i < 4; i++) {
        int bq = m0 + ty * 4 + i;
        #pragma unroll
        for (int j = 0; j < 4; j++) {
            g_W[((size_t)bq * HH + h) * DD + n0 + tx * 4 + j] = acc[i][j];
        }
    }
}

// ---------------------------------------------------------------------------
// Kernel 2b: g_AC[b,h,q,k] = QU(q,h,:).KP(h,k,:) + ccp[q,h] - pm[k]*INV_SCALE
// ---------------------------------------------------------------------------
__global__ void __launch_bounds__(256) ac_kernel(const float* __restrict__ key_mask)
{
    const int bh = blockIdx.z;
    const int b = bh / HH, h = bh % HH;
    const int q0 = blockIdx.x * 64;
    const int k0 = blockIdx.y * 64;
    const int tid = threadIdx.x;
    const int tx = tid % 16, ty = tid / 16;

    __shared__ float a_sm[64 * 33];   // [q][d]
    __shared__ float b_sm[32 * 68];   // [d][k]

    {
        int r = tid / 4, cb = (tid % 4) * 8;
        #pragma unroll
        for (int cc = 0; cc < 8; cc += 4) {
            float4 va = *(const float4*)(g_QU + ((b * LL + q0 + r)) * DD + h * DHH + cb + cc);
            float* dst = a_sm + r * 33 + cb + cc;
            dst[0] = va.x; dst[1] = va.y; dst[2] = va.z; dst[3] = va.w;
        }
    }
    {
        int r = tid / 4, cb = (tid % 4) * 8;
        #pragma unroll
        for (int cc = 0; cc < 8; cc += 4) {
            float4 vb = *(const float4*)(g_KP + ((size_t)(b * HH + h) * LL + k0 + r) * DHH + cb + cc);
            b_sm[(cb + cc + 0) * 68 + r] = vb.x;
            b_sm[(cb + cc + 1) * 68 + r] = vb.y;
            b_sm[(cb + cc + 2) * 68 + r] = vb.z;
            b_sm[(cb + cc + 3) * 68 + r] = vb.w;
        }
    }
    __syncthreads();

    float acc[4][4] = {};
    #pragma unroll
    for (int k = 0; k < 32; k++) {
        float a0 = a_sm[(ty * 4 + 0) * 33 + k];
        float a1 = a_sm[(ty * 4 + 1) * 33 + k];
        float a2 = a_sm[(ty * 4 + 2) * 33 + k];
        float a3 = a_sm[(ty * 4 + 3) * 33 + k];
        float4 bf = *(const float4*)(b_sm + k * 68 + tx * 4);
        acc[0][0] += a0 * bf.x; acc[0][1] += a0 * bf.y; acc[0][2] += a0 * bf.z; acc[0][3] += a0 * bf.w;
        acc[1][0] += a1 * bf.x; acc[1][1] += a1 * bf.y; acc[1][2] += a1 * bf.z; acc[1][3] += a1 * bf.w;
        acc[2][0] += a2 * bf.x; acc[2][1] += a2 * bf.y; acc[2][2] += a2 * bf.z; acc[2][3] += a2 * bf.w;
        acc[3][0] += a3 * bf.x; acc[3][1] += a3 * bf.y; acc[3][2] += a3 * bf.z; acc[3][3] += a3 * bf.w;
    }

    #pragma unroll
    for (int i = 0; i < 4; i++) {
        int qg = q0 + ty * 4 + i;
        float ccp = g_CCP[(b * LL + qg) * HH + h];
        #pragma unroll
        for (int j = 0; j < 4; j++) {
            int kg = k0 + tx * 4 + j;
            float pm = (1.0f - key_mask[b * LL + kg]) * 1e15f;
            g_AC[((size_t)bh * LL + qg) * LL + kg] = acc[i][j] + ccp - pm * INV_SCALE;
        }
    }
}

// ---------------------------------------------------------------------------
// Kernel 3: score2. Block per (q,b); warp owns contiguous 48-k range.
// Barrier-free: pos straight from GMEM (read once, coalesced), W for all 8
// heads in 64 regs (f32x2-packed), fma.rn.f32x2 inner product, 9-SHFL
// multi-head butterfly, per-warp smem transpose, coalesced epilogue.
// ---------------------------------------------------------------------------
__global__ void __launch_bounds__(256, 2) score2_kernel(const float* __restrict__ pos)
{
    __shared__ float sbuf[8][8][52];   // [warp][h][k48 pad52] — write offsets conflict-free

    const int q = blockIdx.x, b = blockIdx.y;
    const int wid = threadIdx.x >> 5, lane = threadIdx.x & 31;
    const int kbase = wid * 48;
    // head index held by this lane after the butterfly
    const int hid = ((lane >> 4) & 1) * 4 + ((lane >> 3) & 1) * 2 + ((lane >> 2) & 1);
    const bool writer = (lane & 3) == 0;

    // W for all 8 heads, this lane's d-slice [lane*8, lane*8+8), packed f32x2
    unsigned long long W2[8][4];
    {
        const float* wp = g_W + ((size_t)(b * LL + q)) * HH * DD + lane * 8;
        #pragma unroll
        for (int h = 0; h < 8; h++) {
            float4 wa = *(const float4*)(wp + h * DD);
            float4 wb = *(const float4*)(wp + h * DD + 4);
            W2[h][0] = pk2(wa.x, wa.y);
            W2[h][1] = pk2(wa.z, wa.w);
            W2[h][2] = pk2(wb.x, wb.y);
            W2[h][3] = pk2(wb.z, wb.w);
        }
    }

    const float* prow = pos + (((size_t)(b * LL + q)) * LL + kbase) * DD + lane * 8;

    #pragma unroll 2
    for (int kl = 0; kl < 48; kl++) {
        float4 p0 = *(const float4*)(prow);
        float4 p1 = *(const float4*)(prow + 4);
        prow += DD;
        unsigned long long P0 = pk2(p0.x, p0.y);
        unsigned long long P1 = pk2(p0.z, p0.w);
        unsigned long long P2 = pk2(p1.x, p1.y);
        unsigned long long P3 = pk2(p1.z, p1.w);

        float r[8];
        #pragma unroll
        for (int h = 0; h < 8; h++) {
            unsigned long long a = mul2(P0, W2[h][0]);
            a = fma2(P1, W2[h][1], a);
            a = fma2(P2, W2[h][2], a);
            a = fma2(P3, W2[h][3], a);
            r[h] = upk_sum(a);
        }

        // 9-SHFL butterfly: reduce 8 head-sums over 32 lanes
        const bool hi16 = (lane & 16) != 0;
        float t0 = hi16 ? r[0] : r[4];
        float t1 = hi16 ? r[1] : r[5];
        float t2 = hi16 ? r[2] : r[6];
        float t3 = hi16 ? r[3] : r[7];
        t0 = __shfl_xor_sync(FULLM, t0, 16);
        t1 = __shfl_xor_sync(FULLM, t1, 16);
        t2 = __shfl_xor_sync(FULLM, t2, 16);
        t3 = __shfl_xor_sync(FULLM, t3, 16);
        float s0 = (hi16 ? r[4] : r[0]) + t0;
        float s1 = (hi16 ? r[5] : r[1]) + t1;
        float s2 = (hi16 ? r[6] : r[2]) + t2;
        float s3 = (hi16 ? r[7] : r[3]) + t3;

        const bool hi8 = (lane & 8) != 0;
        float u0 = hi8 ? s0 : s2;
        float u1 = hi8 ? s1 : s3;
        u0 = __shfl_xor_sync(FULLM, u0, 8);
        u1 = __shfl_xor_sync(FULLM, u1, 8);
        float v0 = (hi8 ? s2 : s0) + u0;
        float v1 = (hi8 ? s3 : s1) + u1;

        const bool hi4 = (lane & 4) != 0;
        float z = hi4 ? v0 : v1;
        z = __shfl_xor_sync(FULLM, z, 4);
        float f = (hi4 ? v1 : v0) + z;

        f += __shfl_xor_sync(FULLM, f, 2);
        f += __shfl_xor_sync(FULLM, f, 1);

        if (writer) sbuf[wid][hid][kl] = f;
    }
    __syncwarp();

    // epilogue: scores = (B_D + AC')*scale  (AC' already has ccp & mask folded)
    #pragma unroll
    for (int h = 0; h < 8; h++) {
        const float* acrow = g_AC + (((size_t)(b * HH + h)) * LL + q) * LL + kbase;
        float*       scrow = g_SC + (((size_t)(b * HH + h)) * LL + q) * LL + kbase;
        float v0 = sbuf[wid][h][lane];
        scrow[lane] = (v0 + acrow[lane]) * SCALE;
        if (lane < 16) {
            float v1 = sbuf[wid][h][32 + lane];
            scrow[32 + lane] = (v1 + acrow[32 + lane]) * SCALE;
        }
    }
}

// ---------------------------------------------------------------------------
// Kernel 4: softmax in-place on g_SC rows. Block per (q,b), warp = head.
// ---------------------------------------------------------------------------
__global__ void __launch_bounds__(256) softmax_kernel()
{
    const int q = blockIdx.x, b = blockIdx.y;
    const int wid = threadIdx.x >> 5, lane = threadIdx.x & 31;

    float* srow = g_SC + (((size_t)(b * HH + wid)) * LL + q) * LL;

    float v[LL / 32];
    float m = -1e30f;
    #pragma unroll
    for (int i = 0; i < LL / 32; i++) {
        v[i] = srow[lane + i * 32];
        m = fmaxf(m, v[i]);
    }
    #pragma unroll
    for (int off = 16; off; off >>= 1)
        m = fmaxf(m, __shfl_xor_sync(FULLM, m, off));

    float s = 0.f;
    #pragma unroll
    for (int i = 0; i < LL / 32; i++) {
        v[i] = __expf(v[i] - m);
        s += v[i];
    }
    #pragma unroll
    for (int off = 16; off; off >>= 1)
        s += __shfl_xor_sync(FULLM, s, off);
    const float rinv = 1.0f / s;

    #pragma unroll
    for (int i = 0; i < LL / 32; i++)
        srow[lane + i * 32] = v[i] * rinv;
}

// ---------------------------------------------------------------------------
// Kernel 5: av. out[b,q,h,:] = P[h,q,:] @ V[b,h,:,:]. Tiled for V reuse.
// grid (12 q-tiles of 32, 16 bh). Block 256: ty=q (0..31), tx=d4 (0..7).
// ---------------------------------------------------------------------------
__global__ void __launch_bounds__(256) av_kernel(float* __restrict__ out)
{
    const int bh = blockIdx.y;
    const int b = bh / HH, h = bh % HH;
    const int q0 = blockIdx.x * 32;
    const int tid = threadIdx.x;
    const int tx = tid % 8, ty = tid / 8;

    __shared__ float p_sm[32 * 68];   // [q][k64]
    __shared__ float v_sm[64 * 32];   // [k][d32] rows = 128B, conflict-free

    float acc[4] = {};

    for (int kc = 0; kc < LL; kc += 64) {
        {   // P chunk: 32 q x 64 k
            int r = tid / 8, c = (tid % 8) * 8;
            const float* src = g_SC + (((size_t)bh) * LL + q0 + r) * LL + kc + c;
            float4 va = *(const float4*)(src);
            float4 vb = *(const float4*)(src + 4);
            *(float4*)(p_sm + r * 68 + c)     = va;
            *(float4*)(p_sm + r * 68 + c + 4) = vb;
        }
        {   // V chunk: 64 k x 32 d
            int r = tid / 4, c = (tid % 4) * 8;
            const float* src = g_VP + (((size_t)bh) * LL + kc + r) * DHH + c;
            float4 va = *(const float4*)(src);
            float4 vb = *(const float4*)(src + 4);
            *(float4*)(v_sm + r * 32 + c)     = va;
            *(float4*)(v_sm + r * 32 + c + 4) = vb;
        }
        __syncthreads();

        #pragma unroll
        for (int k = 0; k < 64; k++) {
            float p = p_sm[ty * 68 + k];
            float4 v4 = *(const float4*)(v_sm + k * 32 + tx * 4);
            acc[0] += p * v4.x; acc[1] += p * v4.y; acc[2] += p * v4.z; acc[3] += p * v4.w;
        }
        __syncthreads();
    }

    float4 o = make_float4(acc[0], acc[1], acc[2], acc[3]);
    *(float4*)(out + ((size_t)(b * LL + q0 + ty)) * DD + h * DHH + tx * 4) = o;
}

// ---------------------------------------------------------------------------
extern "C" void kernel_launch(void* const* d_in, const int* in_sizes, int n_in,
                              void* d_out, int out_size)
{
    const float* key      = (const float*)d_in[0];
    const float* query    = (const float*)d_in[1];
    const float* value    = (const float*)d_in[2];
    const float* pos      = (const float*)d_in[3];
    const float* key_mask = (const float*)d_in[4];
    const float* Wk = (const float*)d_in[5];
    const float* bk = (const float*)d_in[6];
    const float* Wq = (const float*)d_in[7];
    const float* bq = (const float*)d_in[8];
    const float* Wv = (const float*)d_in[9];
    const float* bv = (const float*)d_in[10];
    const float* Wr = (const float*)d_in[11];
    const float* br = (const float*)d_in[12];
    const float* u  = (const float*)d_in[13];
    const float* v  = (const float*)d_in[14];
    float* out = (float*)d_out;

    proj_kernel<<<dim3(24, 8, 3), 256>>>(key, query, value, Wk, bk, Wq, bq, Wv, bv, u, v);
    w_kernel<<<dim3(12, 4, 8), 256>>>(Wr, br);
    ac_kernel<<<dim3(6, 6, 16), 256>>>(key_mask);
    score2_kernel<<<dim3(LL, BB), 256>>>(pos);
    softmax_kernel<<<dim3(LL, BB), 256>>>();
    av_kernel<<<dim3(12, 16), 256>>>(out);
}